// round 12
// baseline (speedup 1.0000x reference)
#include <cuda_runtime.h>
#include <math.h>

#define NR    8192
#define F_IN  128
#define F_OUT 64
#define ALPHA 0.2f
#define LDW   68          // padded row stride (65 used) for scan arrays
#define NSEG  128         // 8192 / 64 element-segments
#define SEGSZ 64
#define NB    1024        // value buckets
#define NCH   8           // chunks (1024 elements each)

// ---------------- scratch (device globals; no allocs allowed) ----------------
__device__ float g_Wh[NR * F_OUT];        // 2 MB
__device__ float g_Whs[NR * F_OUT];       // 2 MB, Wh in sorted order
__device__ float g_s[NR];
__device__ float g_d[NR];
__device__ unsigned g_dmax_u = 0u;             // monotone-uint; idempotent across replays
__device__ unsigned g_dmin_u = 0xFFFFFFFFu;
__device__ int   g_chist[NB * NCH];
__device__ int   g_off[NB + 1];
__device__ int   g_ord[NR];
__device__ float g_dord[NR];
__device__ float g_locPre[NR * LDW];
__device__ float g_locSuf[NR * LDW];
__device__ float g_segPre[NSEG * LDW];
__device__ float g_segSuf[NSEG * LDW];
__device__ float g_offPre[(NSEG + 1) * LDW];
__device__ float g_offSuf[NSEG * LDW];
__device__ unsigned g_barH;                    // monotonic spin-barrier counter
__device__ unsigned g_scanDone;                // monotonic last-block counter

// monotone float<->uint order encoding
__device__ __forceinline__ unsigned encf(float f)
{
    unsigned b = __float_as_uint(f);
    return (b & 0x80000000u) ? ~b : (b | 0x80000000u);
}
__device__ __forceinline__ float decf(unsigned u)
{
    unsigned b = (u & 0x80000000u) ? (u ^ 0x80000000u) : ~u;
    return __uint_as_float(b);
}
__device__ __forceinline__ float mkscale(float dmin, float dmax)
{
    float r = __fsub_rn(dmax, dmin);
    return (r > 0.f) ? __fdiv_rn((float)NB * (1.f - 1e-6f), r) : 0.f;
}
__device__ __forceinline__ float bval(float x, float dmin, float scale)
{
    return fminf(__fmul_rn(__fsub_rn(x, dmin), scale), (float)(NB - 1));
}

// resident-grid barrier; monotonic counter => no reset needed across replays
__device__ __forceinline__ void grid_barrier(unsigned* ctr, unsigned nblk)
{
    __syncthreads();
    if (threadIdx.x == 0) {
        __threadfence();
        unsigned old = atomicAdd(ctr, 1u);
        unsigned target = (old / nblk + 1u) * nblk;
        volatile unsigned* p = ctr;
        while (*p < target) { }
        __threadfence();
    }
    __syncthreads();
}

// ---------------------------------------------------------------------------
// K1: Wh = h @ W ; s = Wh @ a1 ; d = Wh @ a2 ; atomic d-range.
// 128 blocks x 256 threads, 64 rows/block; thread tile 8 rows x 2 cols.
// ---------------------------------------------------------------------------
__global__ __launch_bounds__(256) void wh_kernel(const float* __restrict__ h,
                                                 const float* __restrict__ W,
                                                 const float* __restrict__ a)
{
    __shared__ float h_sh[64][F_IN];      // 32 KB
    __shared__ float W_sh[32][F_OUT];     // 8 KB
    __shared__ float a_sh[2 * F_OUT];
    __shared__ float red[8][2];

    const int tid  = threadIdx.x;
    const int row0 = blockIdx.x * 64;

    const float4* hv  = (const float4*)(h + (size_t)row0 * F_IN);
    float4*       hsv = (float4*)h_sh;
#pragma unroll
    for (int k = 0; k < 8; k++) hsv[tid + k * 256] = hv[tid + k * 256];
    if (tid < 128) a_sh[tid] = a[tid];

    const int cg = tid & 31;
    const int rg = tid >> 5;

    float acc[8][2];
#pragma unroll
    for (int r = 0; r < 8; r++) { acc[r][0] = 0.f; acc[r][1] = 0.f; }

#pragma unroll
    for (int kc = 0; kc < 4; kc++) {
        __syncthreads();
        const float4* Wv = (const float4*)(W + (size_t)kc * 32 * F_OUT);
        float4*      Wsv = (float4*)W_sh;
        Wsv[tid]       = Wv[tid];
        Wsv[tid + 256] = Wv[tid + 256];
        __syncthreads();

#pragma unroll
        for (int k4 = 0; k4 < 8; k4++) {
            const int kk = k4 * 4;
            float4 hr[8];
#pragma unroll
            for (int r = 0; r < 8; r++)
                hr[r] = *(const float4*)&h_sh[rg * 8 + r][kc * 32 + kk];
            float2 wv[4];
#pragma unroll
            for (int q = 0; q < 4; q++)
                wv[q] = *(const float2*)&W_sh[kk + q][cg * 2];
#pragma unroll
            for (int r = 0; r < 8; r++) {
                acc[r][0] = fmaf(hr[r].x, wv[0].x, acc[r][0]);
                acc[r][0] = fmaf(hr[r].y, wv[1].x, acc[r][0]);
                acc[r][0] = fmaf(hr[r].z, wv[2].x, acc[r][0]);
                acc[r][0] = fmaf(hr[r].w, wv[3].x, acc[r][0]);
                acc[r][1] = fmaf(hr[r].x, wv[0].y, acc[r][1]);
                acc[r][1] = fmaf(hr[r].y, wv[1].y, acc[r][1]);
                acc[r][1] = fmaf(hr[r].z, wv[2].y, acc[r][1]);
                acc[r][1] = fmaf(hr[r].w, wv[3].y, acc[r][1]);
            }
        }
    }

#pragma unroll
    for (int r = 0; r < 8; r++) {
        float2 v2 = make_float2(acc[r][0], acc[r][1]);
        *(float2*)&g_Wh[(size_t)(row0 + rg * 8 + r) * F_OUT + cg * 2] = v2;
    }

    const float a10 = a_sh[cg * 2],          a11 = a_sh[cg * 2 + 1];
    const float a20 = a_sh[F_OUT + cg * 2],  a21 = a_sh[F_OUT + cg * 2 + 1];

    float dmn = 1e30f, dmx = -1e30f;
#pragma unroll
    for (int r = 0; r < 8; r++) {
        float p = acc[r][0] * a10 + acc[r][1] * a11;
        float q = acc[r][0] * a20 + acc[r][1] * a21;
#pragma unroll
        for (int o = 16; o; o >>= 1) {
            p += __shfl_xor_sync(~0u, p, o);
            q += __shfl_xor_sync(~0u, q, o);
        }
        if (cg == 0) {
            g_s[row0 + rg * 8 + r] = p;
            g_d[row0 + rg * 8 + r] = q;
        }
        dmn = fminf(dmn, q);
        dmx = fmaxf(dmx, q);
    }
    if (cg == 0) { red[rg][0] = dmn; red[rg][1] = dmx; }
    __syncthreads();
    if (tid == 0) {
        float mn = 1e30f, mx = -1e30f;
#pragma unroll
        for (int w = 0; w < 8; w++) {
            mn = fminf(mn, red[w][0]);
            mx = fmaxf(mx, red[w][1]);
        }
        atomicMin(&g_dmin_u, encf(mn));
        atomicMax(&g_dmax_u, encf(mx));
    }
}

// ---------------------------------------------------------------------------
// K2: fused hist -> barrier(8) -> offset-scan -> stable scatter.
// ---------------------------------------------------------------------------
__global__ __launch_bounds__(1024) void histscatter_kernel()
{
    __shared__ int hist[NB];            // 4 KB (hist phase only)
    __shared__ unsigned wcnt[NB * 8];   // 32 KB: 8 words (32 bytes) per bucket
    __shared__ int choff_sh[NB];        // 4 KB
    __shared__ int warp_sh[32];

    const int t = threadIdx.x, blk = blockIdx.x;
    const int lane = t & 31, warp = t >> 5;

    // ---- hist phase ----
    hist[t] = 0;
    __syncthreads();

    const float dmin  = decf(g_dmin_u);
    const float dmax  = decf(g_dmax_u);
    const float scale = mkscale(dmin, dmax);

    const int   j  = blk * 1024 + t;
    const float dv = g_d[j];
    const int   b  = (int)bval(dv, dmin, scale);
    atomicAdd(&hist[b], 1);
    __syncthreads();

    g_chist[(size_t)t * NCH + blk] = hist[t];

    grid_barrier(&g_barH, NCH);

    // ---- offset scan (each block redundantly; thread t = bucket t) ----
#pragma unroll
    for (int i = 0; i < 8; i++) wcnt[t + i * 1024] = 0u;

    const int4* cp = (const int4*)(g_chist + t * 8);
    int4 v0 = cp[0], v1 = cp[1];
    int vals[8] = {v0.x, v0.y, v0.z, v0.w, v1.x, v1.y, v1.z, v1.w};
    int s = vals[0] + vals[1] + vals[2] + vals[3] +
            vals[4] + vals[5] + vals[6] + vals[7];

    int inc = s;
#pragma unroll
    for (int o = 1; o < 32; o <<= 1) {
        int n = __shfl_up_sync(~0u, inc, o);
        if (lane >= o) inc += n;
    }
    if (lane == 31) warp_sh[warp] = inc;
    __syncthreads();
    if (warp == 0) {
        int ws = warp_sh[lane];
        int wi = ws;
#pragma unroll
        for (int o = 1; o < 32; o <<= 1) {
            int n = __shfl_up_sync(~0u, wi, o);
            if (lane >= o) wi += n;
        }
        warp_sh[lane] = wi - ws;
    }
    __syncthreads();

    int run = warp_sh[warp] + inc - s;   // global start of bucket t
    if (blk == 0) {
        g_off[t] = run;
        if (t == 0) g_off[NB] = NR;
    }
    int myoff = 0;
#pragma unroll
    for (int i = 0; i < 8; i++) {
        if (i == blk) myoff = run;
        run += vals[i];
    }
    choff_sh[t] = myoff;
    __syncthreads();   // wcnt zero + choff_sh visible

    // ---- stable scatter: per-warp uint8 counts + dp4a cross-warp sums ----
    unsigned mask = __match_any_sync(~0u, b);
    const int leader = __ffs(mask) - 1;
    const int lr = __popc(mask & ((1u << lane) - 1));
    if (lane == leader)
        ((unsigned char*)wcnt)[b * 32 + warp] = (unsigned char)__popc(mask);
    __syncthreads();

    const unsigned* row = wcnt + b * 8;
    unsigned cross = 0u;
    const int kf = warp >> 2;
    for (int k = 0; k < kf; k++) cross = __dp4a(row[k], 0x01010101u, cross);
    const unsigned pmask = (1u << ((warp & 3) * 8)) - 1u;
    cross = __dp4a(row[kf] & pmask, 0x01010101u, cross);

    const int pos = choff_sh[b] + (int)cross + lr;
    g_ord[pos]  = j;
    g_dord[pos] = dv;
}

// ---------------------------------------------------------------------------
// K3: per-segment scans (MLP-batched) + write-through sorted Wh (g_Whs)
// + last-block-done inline segscan. 128 blocks x 256 threads.
// ---------------------------------------------------------------------------
__global__ __launch_bounds__(256) void scan_kernel()
{
    __shared__ float wh[SEGSZ][65];   // 16.6 KB
    __shared__ float Bsh[SEGSZ], Dsh[SEGSZ];
    __shared__ int islast_sh;

    const int g = blockIdx.x;
    const int t = threadIdx.x;
    const int base = g * SEGSZ;

    {
        const int row = t >> 2, q = t & 3;   // 4 threads per row, 4 float4 each
        const int src = g_ord[base + row];
        const float4* wr = (const float4*)(g_Wh + (size_t)src * F_OUT) + q * 4;
        float4* ws = (float4*)(g_Whs + (size_t)(base + row) * F_OUT) + q * 4;
#pragma unroll
        for (int i = 0; i < 4; i++) {
            float4 v = wr[i];
            ws[i] = v;                        // sorted-order Wh for final
            wh[row][q * 16 + i * 4 + 0] = v.x;
            wh[row][q * 16 + i * 4 + 1] = v.y;
            wh[row][q * 16 + i * 4 + 2] = v.z;
            wh[row][q * 16 + i * 4 + 3] = v.w;
        }
    }
    if (t < SEGSZ) {
        const float dmax = decf(g_dmax_u);
        float dv = g_dord[base + t];
        Bsh[t] = __expf(dv - dmax);
        Dsh[t] = __expf(ALPHA * (dv - dmax));
    }
    __syncthreads();

    if (t < 65) {
        float acc = 0.f;
#pragma unroll
        for (int kb = 0; kb < SEGSZ; kb += 8) {
            float xv[8], dw[8];
#pragma unroll
            for (int i = 0; i < 8; i++) {
                xv[i] = (t < 64) ? wh[kb + i][t] : 1.f;
                dw[i] = Dsh[kb + i];
            }
#pragma unroll
            for (int i = 0; i < 8; i++) {
                g_locPre[(size_t)(base + kb + i) * LDW + t] = acc;
                acc = fmaf(dw[i], xv[i], acc);
            }
        }
        g_segPre[g * LDW + t] = acc;
    } else if (t >= 128 && t < 193) {
        const int tt = t - 128;
        float acc2 = 0.f;
#pragma unroll
        for (int kb = SEGSZ - 8; kb >= 0; kb -= 8) {
            float xv[8], bw[8];
#pragma unroll
            for (int i = 7; i >= 0; i--) {
                xv[i] = (tt < 64) ? wh[kb + i][tt] : 1.f;
                bw[i] = Bsh[kb + i];
            }
#pragma unroll
            for (int i = 7; i >= 0; i--) {
                acc2 = fmaf(bw[i], xv[i], acc2);
                g_locSuf[(size_t)(base + kb + i) * LDW + tt] = acc2;
            }
        }
        g_segSuf[g * LDW + tt] = acc2;
    }

    // ---- last-block-done: inline segscan ----
    __syncthreads();
    if (t == 0) {
        __threadfence();
        unsigned old = atomicAdd(&g_scanDone, 1u);
        islast_sh = ((old % NSEG) == (NSEG - 1)) ? 1 : 0;
    }
    __syncthreads();
    if (!islast_sh) return;
    __threadfence();

    if (t < 65) {
        float acc = 0.f;
#pragma unroll
        for (int half = 0; half < 2; half++) {
            float vp[64];
#pragma unroll
            for (int g2 = 0; g2 < 64; g2++)
                vp[g2] = g_segPre[(half * 64 + g2) * LDW + t];
#pragma unroll
            for (int g2 = 0; g2 < 64; g2++) {
                g_offPre[(half * 64 + g2) * LDW + t] = acc;
                acc += vp[g2];
            }
        }
        g_offPre[NSEG * LDW + t] = acc;
    } else if (t >= 128 && t < 193) {
        const int tt = t - 128;
        float acc2 = 0.f;
#pragma unroll
        for (int half = 1; half >= 0; half--) {
            float vs[64];
#pragma unroll
            for (int g2 = 0; g2 < 64; g2++)
                vs[g2] = g_segSuf[(half * 64 + g2) * LDW + tt];
#pragma unroll
            for (int g2 = 63; g2 >= 0; g2--) {
                g_offSuf[(half * 64 + g2) * LDW + tt] = acc2;
                acc2 += vs[g2];
            }
        }
    }
}

// ---------------------------------------------------------------------------
// K4: warp-per-row combine; boundary bucket batched (MLP=8, no indirection);
// ELU via __expf.
// ---------------------------------------------------------------------------
__global__ __launch_bounds__(256) void final_kernel(float* __restrict__ out)
{
    const int t = threadIdx.x;
    const int w = t >> 5, l = t & 31;
    const int i = blockIdx.x * 8 + w;

    const float dmax  = decf(g_dmax_u);
    const float dmin  = decf(g_dmin_u);
    const float scale = mkscale(dmin, dmax);

    const float s  = g_s[i];
    const float xm = s + dmax;
    const float m  = fmaxf(xm, ALPHA * xm);
    const float A  = __expf(xm - m);
    const float C  = __expf(ALPHA * xm - m);
    const float th = -s;

    const float tb = bval(th, dmin, scale);
    int e0 = 0, e1 = 0;
    if (tb >= 0.f) {
        int b = (int)tb;
        e0 = g_off[b];
        e1 = g_off[b + 1];
    }

    float pre_l, pre_h, pre_z;
    if (e0 < NR) {
        const int sg = e0 >> 6;
        const float* oP = g_offPre + sg * LDW;
        const float* lP = g_locPre + (size_t)e0 * LDW;
        pre_l = oP[l] + lP[l];
        pre_h = oP[32 + l] + lP[32 + l];
        pre_z = oP[64] + lP[64];
    } else {
        const float* oP = g_offPre + NSEG * LDW;
        pre_l = oP[l];
        pre_h = oP[32 + l];
        pre_z = oP[64];
    }

    float suf_l = 0.f, suf_h = 0.f, suf_z = 0.f;
    if (e1 < NR) {
        const int sg = e1 >> 6;
        const float* oS = g_offSuf + sg * LDW;
        const float* lS = g_locSuf + (size_t)e1 * LDW;
        suf_l = oS[l] + lS[l];
        suf_h = oS[32 + l] + lS[32 + l];
        suf_z = oS[64] + lS[64];
    }

    // boundary bucket: 4-element batches, all loads independent (no je chain)
    for (int e = e0; e < e1; e += 4) {
        const int n = min(4, e1 - e);
        float de_[4], x1_[4], x2_[4];
#pragma unroll
        for (int k = 0; k < 4; k++) {
            if (k < n) {
                de_[k] = g_dord[e + k];
                const float* wr = g_Whs + (size_t)(e + k) * F_OUT;
                x1_[k] = wr[l];
                x2_[k] = wr[32 + l];
            }
        }
#pragma unroll
        for (int k = 0; k < 4; k++) {
            if (k < n) {
                if (de_[k] <= th) {
                    const float wd = __expf(ALPHA * (de_[k] - dmax));
                    pre_l = fmaf(wd, x1_[k], pre_l);
                    pre_h = fmaf(wd, x2_[k], pre_h);
                    pre_z += wd;
                } else {
                    const float wb = __expf(de_[k] - dmax);
                    suf_l = fmaf(wb, x1_[k], suf_l);
                    suf_h = fmaf(wb, x2_[k], suf_h);
                    suf_z += wb;
                }
            }
        }
    }

    const float Z  = fmaf(A, suf_z, C * pre_z);
    const float rz = 1.f / Z;
    const float v1 = fmaf(A, suf_l, C * pre_l) * rz;
    const float v2 = fmaf(A, suf_h, C * pre_h) * rz;

    out[(size_t)i * F_OUT + l]      = (v1 > 0.f) ? v1 : (__expf(v1) - 1.f);
    out[(size_t)i * F_OUT + 32 + l] = (v2 > 0.f) ? v2 : (__expf(v2) - 1.f);
}

// ---------------------------------------------------------------------------
extern "C" void kernel_launch(void* const* d_in, const int* in_sizes, int n_in,
                              void* d_out, int out_size)
{
    const float* h = (const float*)d_in[0];
    const float* W = (const float*)d_in[1];
    const float* a = (const float*)d_in[2];
    float* out = (float*)d_out;

    wh_kernel<<<NR / 64, 256>>>(h, W, a);
    histscatter_kernel<<<NCH, 1024>>>();
    scan_kernel<<<NSEG, 256>>>();
    final_kernel<<<NR / 8, 256>>>(out);
}

// round 13
// speedup vs baseline: 1.0069x; 1.0069x over previous
#include <cuda_runtime.h>
#include <math.h>

#define NR    8192
#define F_IN  128
#define F_OUT 64
#define ALPHA 0.2f
#define LDW   68          // padded row stride (65 used) for scan arrays
#define NSEG  128         // 8192 / 64 element-segments
#define SEGSZ 64
#define NB    1024        // value buckets
#define NCH   8           // chunks (1024 elements each)

// ---------------- scratch (device globals; no allocs allowed) ----------------
__device__ float g_Wh[NR * F_OUT];        // 2 MB
__device__ float g_s[NR];
__device__ float g_d[NR];
__device__ unsigned g_dmax_u = 0u;             // monotone-uint; idempotent across replays
__device__ unsigned g_dmin_u = 0xFFFFFFFFu;
__device__ int   g_chist[NB * NCH];
__device__ int   g_off[NB + 1];
__device__ int   g_ord[NR];       // bucket-stable order (pre-sort)
__device__ float g_dord[NR];
__device__ int   g_ord2[NR];      // fully value-sorted order
__device__ float g_dord2[NR];
__device__ float g_locPre[NR * LDW];
__device__ float g_locSuf[NR * LDW];
__device__ float g_segPre[NSEG * LDW];
__device__ float g_segSuf[NSEG * LDW];
__device__ float g_offPre[(NSEG + 1) * LDW];
__device__ float g_offSuf[NSEG * LDW];
__device__ unsigned g_barH;                    // monotonic spin-barrier counter
__device__ unsigned g_scanDone;                // monotonic last-block counter

// monotone float<->uint order encoding
__device__ __forceinline__ unsigned encf(float f)
{
    unsigned b = __float_as_uint(f);
    return (b & 0x80000000u) ? ~b : (b | 0x80000000u);
}
__device__ __forceinline__ float decf(unsigned u)
{
    unsigned b = (u & 0x80000000u) ? (u ^ 0x80000000u) : ~u;
    return __uint_as_float(b);
}
__device__ __forceinline__ float mkscale(float dmin, float dmax)
{
    float r = __fsub_rn(dmax, dmin);
    return (r > 0.f) ? __fdiv_rn((float)NB * (1.f - 1e-6f), r) : 0.f;
}
__device__ __forceinline__ float bval(float x, float dmin, float scale)
{
    return fminf(__fmul_rn(__fsub_rn(x, dmin), scale), (float)(NB - 1));
}

// resident-grid barrier; monotonic counter => safe across replays AND safe for
// multiple consecutive barrier rounds on the same counter
__device__ __forceinline__ void grid_barrier(unsigned* ctr, unsigned nblk)
{
    __syncthreads();
    if (threadIdx.x == 0) {
        __threadfence();
        unsigned old = atomicAdd(ctr, 1u);
        unsigned target = (old / nblk + 1u) * nblk;
        volatile unsigned* p = ctr;
        while (*p < target) { }
        __threadfence();
    }
    __syncthreads();
}

// ---------------------------------------------------------------------------
// K1: Wh = h @ W ; s = Wh @ a1 ; d = Wh @ a2 ; atomic d-range.
// ---------------------------------------------------------------------------
__global__ __launch_bounds__(256) void wh_kernel(const float* __restrict__ h,
                                                 const float* __restrict__ W,
                                                 const float* __restrict__ a)
{
    __shared__ float h_sh[64][F_IN];      // 32 KB
    __shared__ float W_sh[32][F_OUT];     // 8 KB
    __shared__ float a_sh[2 * F_OUT];
    __shared__ float red[8][2];

    const int tid  = threadIdx.x;
    const int row0 = blockIdx.x * 64;

    const float4* hv  = (const float4*)(h + (size_t)row0 * F_IN);
    float4*       hsv = (float4*)h_sh;
#pragma unroll
    for (int k = 0; k < 8; k++) hsv[tid + k * 256] = hv[tid + k * 256];
    if (tid < 128) a_sh[tid] = a[tid];

    const int cg = tid & 31;
    const int rg = tid >> 5;

    float acc[8][2];
#pragma unroll
    for (int r = 0; r < 8; r++) { acc[r][0] = 0.f; acc[r][1] = 0.f; }

#pragma unroll
    for (int kc = 0; kc < 4; kc++) {
        __syncthreads();
        const float4* Wv = (const float4*)(W + (size_t)kc * 32 * F_OUT);
        float4*      Wsv = (float4*)W_sh;
        Wsv[tid]       = Wv[tid];
        Wsv[tid + 256] = Wv[tid + 256];
        __syncthreads();

#pragma unroll
        for (int k4 = 0; k4 < 8; k4++) {
            const int kk = k4 * 4;
            float4 hr[8];
#pragma unroll
            for (int r = 0; r < 8; r++)
                hr[r] = *(const float4*)&h_sh[rg * 8 + r][kc * 32 + kk];
            float2 wv[4];
#pragma unroll
            for (int q = 0; q < 4; q++)
                wv[q] = *(const float2*)&W_sh[kk + q][cg * 2];
#pragma unroll
            for (int r = 0; r < 8; r++) {
                acc[r][0] = fmaf(hr[r].x, wv[0].x, acc[r][0]);
                acc[r][0] = fmaf(hr[r].y, wv[1].x, acc[r][0]);
                acc[r][0] = fmaf(hr[r].z, wv[2].x, acc[r][0]);
                acc[r][0] = fmaf(hr[r].w, wv[3].x, acc[r][0]);
                acc[r][1] = fmaf(hr[r].x, wv[0].y, acc[r][1]);
                acc[r][1] = fmaf(hr[r].y, wv[1].y, acc[r][1]);
                acc[r][1] = fmaf(hr[r].z, wv[2].y, acc[r][1]);
                acc[r][1] = fmaf(hr[r].w, wv[3].y, acc[r][1]);
            }
        }
    }

#pragma unroll
    for (int r = 0; r < 8; r++) {
        float2 v2 = make_float2(acc[r][0], acc[r][1]);
        *(float2*)&g_Wh[(size_t)(row0 + rg * 8 + r) * F_OUT + cg * 2] = v2;
    }

    const float a10 = a_sh[cg * 2],          a11 = a_sh[cg * 2 + 1];
    const float a20 = a_sh[F_OUT + cg * 2],  a21 = a_sh[F_OUT + cg * 2 + 1];

    float dmn = 1e30f, dmx = -1e30f;
#pragma unroll
    for (int r = 0; r < 8; r++) {
        float p = acc[r][0] * a10 + acc[r][1] * a11;
        float q = acc[r][0] * a20 + acc[r][1] * a21;
#pragma unroll
        for (int o = 16; o; o >>= 1) {
            p += __shfl_xor_sync(~0u, p, o);
            q += __shfl_xor_sync(~0u, q, o);
        }
        if (cg == 0) {
            g_s[row0 + rg * 8 + r] = p;
            g_d[row0 + rg * 8 + r] = q;
        }
        dmn = fminf(dmn, q);
        dmx = fmaxf(dmx, q);
    }
    if (cg == 0) { red[rg][0] = dmn; red[rg][1] = dmx; }
    __syncthreads();
    if (tid == 0) {
        float mn = 1e30f, mx = -1e30f;
#pragma unroll
        for (int w = 0; w < 8; w++) {
            mn = fminf(mn, red[w][0]);
            mx = fmaxf(mx, red[w][1]);
        }
        atomicMin(&g_dmin_u, encf(mn));
        atomicMax(&g_dmax_u, encf(mx));
    }
}

// ---------------------------------------------------------------------------
// K2: fused hist -> barrier -> offset-scan -> stable scatter -> barrier ->
// in-bucket value sort (deterministic by (d, idx)). 8 blocks x 1024 threads.
// ---------------------------------------------------------------------------
__global__ __launch_bounds__(1024) void histscatter_kernel()
{
    __shared__ int hist[NB];            // 4 KB (hist phase only)
    __shared__ unsigned wcnt[NB * 8];   // 32 KB: 8 words (32 bytes) per bucket
    __shared__ int choff_sh[NB];        // 4 KB
    __shared__ int warp_sh[32];

    const int t = threadIdx.x, blk = blockIdx.x;
    const int lane = t & 31, warp = t >> 5;

    // ---- hist phase ----
    hist[t] = 0;
    __syncthreads();

    const float dmin  = decf(g_dmin_u);
    const float dmax  = decf(g_dmax_u);
    const float scale = mkscale(dmin, dmax);

    const int   j  = blk * 1024 + t;
    const float dv = g_d[j];
    const int   b  = (int)bval(dv, dmin, scale);
    atomicAdd(&hist[b], 1);
    __syncthreads();

    g_chist[(size_t)t * NCH + blk] = hist[t];

    grid_barrier(&g_barH, NCH);

    // ---- offset scan (each block redundantly; thread t = bucket t) ----
#pragma unroll
    for (int i = 0; i < 8; i++) wcnt[t + i * 1024] = 0u;

    const int4* cp = (const int4*)(g_chist + t * 8);
    int4 v0 = cp[0], v1 = cp[1];
    int vals[8] = {v0.x, v0.y, v0.z, v0.w, v1.x, v1.y, v1.z, v1.w};
    int s = vals[0] + vals[1] + vals[2] + vals[3] +
            vals[4] + vals[5] + vals[6] + vals[7];

    int inc = s;
#pragma unroll
    for (int o = 1; o < 32; o <<= 1) {
        int n = __shfl_up_sync(~0u, inc, o);
        if (lane >= o) inc += n;
    }
    if (lane == 31) warp_sh[warp] = inc;
    __syncthreads();
    if (warp == 0) {
        int ws = warp_sh[lane];
        int wi = ws;
#pragma unroll
        for (int o = 1; o < 32; o <<= 1) {
            int n = __shfl_up_sync(~0u, wi, o);
            if (lane >= o) wi += n;
        }
        warp_sh[lane] = wi - ws;
    }
    __syncthreads();

    int run = warp_sh[warp] + inc - s;   // global start of bucket t
    if (blk == 0) {
        g_off[t] = run;
        if (t == 0) g_off[NB] = NR;
    }
    int myoff = 0;
#pragma unroll
    for (int i = 0; i < 8; i++) {
        if (i == blk) myoff = run;
        run += vals[i];
    }
    choff_sh[t] = myoff;
    __syncthreads();   // wcnt zero + choff_sh visible

    // ---- stable scatter: per-warp uint8 counts + dp4a cross-warp sums ----
    unsigned mask = __match_any_sync(~0u, b);
    const int leader = __ffs(mask) - 1;
    const int lr = __popc(mask & ((1u << lane) - 1));
    if (lane == leader)
        ((unsigned char*)wcnt)[b * 32 + warp] = (unsigned char)__popc(mask);
    __syncthreads();

    const unsigned* row = wcnt + b * 8;
    unsigned cross = 0u;
    const int kf = warp >> 2;
    for (int k = 0; k < kf; k++) cross = __dp4a(row[k], 0x01010101u, cross);
    const unsigned pmask = (1u << ((warp & 3) * 8)) - 1u;
    cross = __dp4a(row[kf] & pmask, 0x01010101u, cross);

    const int pos = choff_sh[b] + (int)cross + lr;
    g_ord[pos]  = j;
    g_dord[pos] = dv;

    grid_barrier(&g_barH, NCH);

    // ---- in-bucket value sort: 256 warps, 4 buckets each; rank-by-count ----
#pragma unroll
    for (int q = 0; q < 4; q++) {
        const int b2 = blk * 128 + warp * 4 + q;
        const int s0 = g_off[b2];
        const int n  = g_off[b2 + 1] - s0;
        for (int e = lane; e < n; e += 32) {
            const float dk = g_dord[s0 + e];
            const int   ik = g_ord[s0 + e];
            int rank = 0;
            for (int e2 = 0; e2 < n; e2++) {
                const float d2 = g_dord[s0 + e2];
                const int   i2 = g_ord[s0 + e2];
                rank += (d2 < dk) || (d2 == dk && i2 < ik);
            }
            g_dord2[s0 + rank] = dk;
            g_ord2[s0 + rank]  = ik;
        }
    }
}

// ---------------------------------------------------------------------------
// K3: per-segment scans over the value-sorted order (MLP-batched)
// + last-block-done inline segscan. 128 blocks x 256 threads.
// ---------------------------------------------------------------------------
__global__ __launch_bounds__(256) void scan_kernel()
{
    __shared__ float wh[SEGSZ][65];   // 16.6 KB
    __shared__ float Bsh[SEGSZ], Dsh[SEGSZ];
    __shared__ int islast_sh;

    const int g = blockIdx.x;
    const int t = threadIdx.x;
    const int base = g * SEGSZ;

    {
        const int row = t >> 2, q = t & 3;   // 4 threads per row, 4 float4 each
        const int src = g_ord2[base + row];
        const float4* wr = (const float4*)(g_Wh + (size_t)src * F_OUT) + q * 4;
#pragma unroll
        for (int i = 0; i < 4; i++) {
            float4 v = wr[i];
            wh[row][q * 16 + i * 4 + 0] = v.x;
            wh[row][q * 16 + i * 4 + 1] = v.y;
            wh[row][q * 16 + i * 4 + 2] = v.z;
            wh[row][q * 16 + i * 4 + 3] = v.w;
        }
    }
    if (t < SEGSZ) {
        const float dmax = decf(g_dmax_u);
        float dv = g_dord2[base + t];
        Bsh[t] = __expf(dv - dmax);
        Dsh[t] = __expf(ALPHA * (dv - dmax));
    }
    __syncthreads();

    if (t < 65) {
        float acc = 0.f;
#pragma unroll
        for (int kb = 0; kb < SEGSZ; kb += 8) {
            float xv[8], dw[8];
#pragma unroll
            for (int i = 0; i < 8; i++) {
                xv[i] = (t < 64) ? wh[kb + i][t] : 1.f;
                dw[i] = Dsh[kb + i];
            }
#pragma unroll
            for (int i = 0; i < 8; i++) {
                g_locPre[(size_t)(base + kb + i) * LDW + t] = acc;
                acc = fmaf(dw[i], xv[i], acc);
            }
        }
        g_segPre[g * LDW + t] = acc;
    } else if (t >= 128 && t < 193) {
        const int tt = t - 128;
        float acc2 = 0.f;
#pragma unroll
        for (int kb = SEGSZ - 8; kb >= 0; kb -= 8) {
            float xv[8], bw[8];
#pragma unroll
            for (int i = 7; i >= 0; i--) {
                xv[i] = (tt < 64) ? wh[kb + i][tt] : 1.f;
                bw[i] = Bsh[kb + i];
            }
#pragma unroll
            for (int i = 7; i >= 0; i--) {
                acc2 = fmaf(bw[i], xv[i], acc2);
                g_locSuf[(size_t)(base + kb + i) * LDW + tt] = acc2;
            }
        }
        g_segSuf[g * LDW + tt] = acc2;
    }

    // ---- last-block-done: inline segscan ----
    __syncthreads();
    if (t == 0) {
        __threadfence();
        unsigned old = atomicAdd(&g_scanDone, 1u);
        islast_sh = ((old % NSEG) == (NSEG - 1)) ? 1 : 0;
    }
    __syncthreads();
    if (!islast_sh) return;
    __threadfence();

    if (t < 65) {
        float acc = 0.f;
#pragma unroll
        for (int half = 0; half < 2; half++) {
            float vp[64];
#pragma unroll
            for (int g2 = 0; g2 < 64; g2++)
                vp[g2] = g_segPre[(half * 64 + g2) * LDW + t];
#pragma unroll
            for (int g2 = 0; g2 < 64; g2++) {
                g_offPre[(half * 64 + g2) * LDW + t] = acc;
                acc += vp[g2];
            }
        }
        g_offPre[NSEG * LDW + t] = acc;
    } else if (t >= 128 && t < 193) {
        const int tt = t - 128;
        float acc2 = 0.f;
#pragma unroll
        for (int half = 1; half >= 0; half--) {
            float vs[64];
#pragma unroll
            for (int g2 = 0; g2 < 64; g2++)
                vs[g2] = g_segSuf[(half * 64 + g2) * LDW + tt];
#pragma unroll
            for (int g2 = 63; g2 >= 0; g2--) {
                g_offSuf[(half * 64 + g2) * LDW + tt] = acc2;
                acc2 += vs[g2];
            }
        }
    }
}

// ---------------------------------------------------------------------------
// K4: warp-per-row combine. Split via bucket lookup + short in-bucket binary
// search over the value-sorted g_dord2 (warp-uniform). No per-element work.
// ---------------------------------------------------------------------------
__global__ __launch_bounds__(256) void final_kernel(float* __restrict__ out)
{
    const int t = threadIdx.x;
    const int w = t >> 5, l = t & 31;
    const int i = blockIdx.x * 8 + w;

    const float dmax  = decf(g_dmax_u);
    const float dmin  = decf(g_dmin_u);
    const float scale = mkscale(dmin, dmax);

    const float s  = g_s[i];
    const float xm = s + dmax;
    const float m  = fmaxf(xm, ALPHA * xm);
    const float A  = __expf(xm - m);
    const float C  = __expf(ALPHA * xm - m);
    const float th = -s;

    // split position: count of d_j <= th (value-sorted order)
    const float tb = bval(th, dmin, scale);
    int tpos = 0;
    if (tb >= 0.f) {
        const int b = (int)tb;
        int lo = g_off[b], hi = g_off[b + 1];
        while (lo < hi) {
            int mid = (lo + hi) >> 1;
            if (g_dord2[mid] <= th) lo = mid + 1; else hi = mid;
        }
        tpos = lo;
    }

    float pre_l, pre_h, pre_z;
    if (tpos < NR) {
        const int sg = tpos >> 6;
        const float* oP = g_offPre + sg * LDW;
        const float* lP = g_locPre + (size_t)tpos * LDW;
        pre_l = oP[l] + lP[l];
        pre_h = oP[32 + l] + lP[32 + l];
        pre_z = oP[64] + lP[64];
    } else {
        const float* oP = g_offPre + NSEG * LDW;
        pre_l = oP[l];
        pre_h = oP[32 + l];
        pre_z = oP[64];
    }

    float suf_l = 0.f, suf_h = 0.f, suf_z = 0.f;
    if (tpos < NR) {
        const int sg = tpos >> 6;
        const float* oS = g_offSuf + sg * LDW;
        const float* lS = g_locSuf + (size_t)tpos * LDW;
        suf_l = oS[l] + lS[l];
        suf_h = oS[32 + l] + lS[32 + l];
        suf_z = oS[64] + lS[64];
    }

    const float Z  = fmaf(A, suf_z, C * pre_z);
    const float rz = 1.f / Z;
    const float v1 = fmaf(A, suf_l, C * pre_l) * rz;
    const float v2 = fmaf(A, suf_h, C * pre_h) * rz;

    out[(size_t)i * F_OUT + l]      = (v1 > 0.f) ? v1 : (__expf(v1) - 1.f);
    out[(size_t)i * F_OUT + 32 + l] = (v2 > 0.f) ? v2 : (__expf(v2) - 1.f);
}

// ---------------------------------------------------------------------------
extern "C" void kernel_launch(void* const* d_in, const int* in_sizes, int n_in,
                              void* d_out, int out_size)
{
    const float* h = (const float*)d_in[0];
    const float* W = (const float*)d_in[1];
    const float* a = (const float*)d_in[2];
    float* out = (float*)d_out;

    wh_kernel<<<NR / 64, 256>>>(h, W, a);
    histscatter_kernel<<<NCH, 1024>>>();
    scan_kernel<<<NSEG, 256>>>();
    final_kernel<<<NR / 8, 256>>>(out);
}

// round 14
// speedup vs baseline: 1.0095x; 1.0026x over previous
#include <cuda_runtime.h>
#include <math.h>

#define NR    8192
#define F_IN  128
#define F_OUT 64
#define ALPHA 0.2f
#define LDW   68          // padded row stride (65 used) for scan arrays
#define NSEG  128         // 8192 / 64 element-segments
#define SEGSZ 64
#define NB    1024        // value buckets
#define NCH   8           // chunks (1024 elements each)

// ---------------- scratch (device globals; no allocs allowed) ----------------
__device__ float g_Wh[NR * F_OUT];        // 2 MB
__device__ float g_s[NR];
__device__ float g_d[NR];
__device__ unsigned g_dmax_u = 0u;             // monotone-uint; idempotent across replays
__device__ unsigned g_dmin_u = 0xFFFFFFFFu;
__device__ int   g_chist[NB * NCH];
__device__ int   g_off[NB + 1];
__device__ int   g_ord[NR];       // bucket-stable order (pre-sort)
__device__ float g_dord[NR];
__device__ int   g_ord2[NR];      // fully value-sorted order
__device__ float g_dord2[NR];
__device__ float g_locPre[NR * LDW];
__device__ float g_locSuf[NR * LDW];
__device__ float g_segPre[NSEG * LDW];
__device__ float g_segSuf[NSEG * LDW];
__device__ float g_offPre[(NSEG + 1) * LDW];
__device__ float g_offSuf[NSEG * LDW];
__device__ unsigned g_barH;                    // monotonic spin-barrier counter
__device__ unsigned g_scanDone;                // monotonic last-block counter

// monotone float<->uint order encoding
__device__ __forceinline__ unsigned encf(float f)
{
    unsigned b = __float_as_uint(f);
    return (b & 0x80000000u) ? ~b : (b | 0x80000000u);
}
__device__ __forceinline__ float decf(unsigned u)
{
    unsigned b = (u & 0x80000000u) ? (u ^ 0x80000000u) : ~u;
    return __uint_as_float(b);
}
__device__ __forceinline__ float mkscale(float dmin, float dmax)
{
    float r = __fsub_rn(dmax, dmin);
    return (r > 0.f) ? __fdiv_rn((float)NB * (1.f - 1e-6f), r) : 0.f;
}
__device__ __forceinline__ float bval(float x, float dmin, float scale)
{
    return fminf(__fmul_rn(__fsub_rn(x, dmin), scale), (float)(NB - 1));
}

// resident-grid barrier; monotonic counter => safe across replays and rounds
__device__ __forceinline__ void grid_barrier(unsigned* ctr, unsigned nblk)
{
    __syncthreads();
    if (threadIdx.x == 0) {
        __threadfence();
        unsigned old = atomicAdd(ctr, 1u);
        unsigned target = (old / nblk + 1u) * nblk;
        volatile unsigned* p = ctr;
        while (*p < target) { }
        __threadfence();
    }
    __syncthreads();
}

// ---------------------------------------------------------------------------
// K1: Wh = h @ W ; s = Wh @ a1 ; d = Wh @ a2 ; atomic d-range.
// ---------------------------------------------------------------------------
__global__ __launch_bounds__(256) void wh_kernel(const float* __restrict__ h,
                                                 const float* __restrict__ W,
                                                 const float* __restrict__ a)
{
    __shared__ float h_sh[64][F_IN];      // 32 KB
    __shared__ float W_sh[32][F_OUT];     // 8 KB
    __shared__ float a_sh[2 * F_OUT];
    __shared__ float red[8][2];

    const int tid  = threadIdx.x;
    const int row0 = blockIdx.x * 64;

    const float4* hv  = (const float4*)(h + (size_t)row0 * F_IN);
    float4*       hsv = (float4*)h_sh;
#pragma unroll
    for (int k = 0; k < 8; k++) hsv[tid + k * 256] = hv[tid + k * 256];
    if (tid < 128) a_sh[tid] = a[tid];

    const int cg = tid & 31;
    const int rg = tid >> 5;

    float acc[8][2];
#pragma unroll
    for (int r = 0; r < 8; r++) { acc[r][0] = 0.f; acc[r][1] = 0.f; }

#pragma unroll
    for (int kc = 0; kc < 4; kc++) {
        __syncthreads();
        const float4* Wv = (const float4*)(W + (size_t)kc * 32 * F_OUT);
        float4*      Wsv = (float4*)W_sh;
        Wsv[tid]       = Wv[tid];
        Wsv[tid + 256] = Wv[tid + 256];
        __syncthreads();

#pragma unroll
        for (int k4 = 0; k4 < 8; k4++) {
            const int kk = k4 * 4;
            float4 hr[8];
#pragma unroll
            for (int r = 0; r < 8; r++)
                hr[r] = *(const float4*)&h_sh[rg * 8 + r][kc * 32 + kk];
            float2 wv[4];
#pragma unroll
            for (int q = 0; q < 4; q++)
                wv[q] = *(const float2*)&W_sh[kk + q][cg * 2];
#pragma unroll
            for (int r = 0; r < 8; r++) {
                acc[r][0] = fmaf(hr[r].x, wv[0].x, acc[r][0]);
                acc[r][0] = fmaf(hr[r].y, wv[1].x, acc[r][0]);
                acc[r][0] = fmaf(hr[r].z, wv[2].x, acc[r][0]);
                acc[r][0] = fmaf(hr[r].w, wv[3].x, acc[r][0]);
                acc[r][1] = fmaf(hr[r].x, wv[0].y, acc[r][1]);
                acc[r][1] = fmaf(hr[r].y, wv[1].y, acc[r][1]);
                acc[r][1] = fmaf(hr[r].z, wv[2].y, acc[r][1]);
                acc[r][1] = fmaf(hr[r].w, wv[3].y, acc[r][1]);
            }
        }
    }

#pragma unroll
    for (int r = 0; r < 8; r++) {
        float2 v2 = make_float2(acc[r][0], acc[r][1]);
        *(float2*)&g_Wh[(size_t)(row0 + rg * 8 + r) * F_OUT + cg * 2] = v2;
    }

    const float a10 = a_sh[cg * 2],          a11 = a_sh[cg * 2 + 1];
    const float a20 = a_sh[F_OUT + cg * 2],  a21 = a_sh[F_OUT + cg * 2 + 1];

    float dmn = 1e30f, dmx = -1e30f;
#pragma unroll
    for (int r = 0; r < 8; r++) {
        float p = acc[r][0] * a10 + acc[r][1] * a11;
        float q = acc[r][0] * a20 + acc[r][1] * a21;
#pragma unroll
        for (int o = 16; o; o >>= 1) {
            p += __shfl_xor_sync(~0u, p, o);
            q += __shfl_xor_sync(~0u, q, o);
        }
        if (cg == 0) {
            g_s[row0 + rg * 8 + r] = p;
            g_d[row0 + rg * 8 + r] = q;
        }
        dmn = fminf(dmn, q);
        dmx = fmaxf(dmx, q);
    }
    if (cg == 0) { red[rg][0] = dmn; red[rg][1] = dmx; }
    __syncthreads();
    if (tid == 0) {
        float mn = 1e30f, mx = -1e30f;
#pragma unroll
        for (int w = 0; w < 8; w++) {
            mn = fminf(mn, red[w][0]);
            mx = fmaxf(mx, red[w][1]);
        }
        atomicMin(&g_dmin_u, encf(mn));
        atomicMax(&g_dmax_u, encf(mx));
    }
}

// ---------------------------------------------------------------------------
// K2: fused hist -> barrier -> offset-scan -> stable scatter -> barrier ->
// in-bucket value sort via smem staging. 8 blocks x 1024 threads.
// ---------------------------------------------------------------------------
__global__ __launch_bounds__(1024) void histscatter_kernel()
{
    __shared__ int hist[NB];            // 4 KB (hist phase only)
    __shared__ unsigned wcnt[NB * 8];   // 32 KB; reused as sort staging later
    __shared__ int choff_sh[NB];        // 4 KB
    __shared__ int warp_sh[32];

    const int t = threadIdx.x, blk = blockIdx.x;
    const int lane = t & 31, warp = t >> 5;

    // ---- hist phase ----
    hist[t] = 0;
    __syncthreads();

    const float dmin  = decf(g_dmin_u);
    const float dmax  = decf(g_dmax_u);
    const float scale = mkscale(dmin, dmax);

    const int   j  = blk * 1024 + t;
    const float dv = g_d[j];
    const int   b  = (int)bval(dv, dmin, scale);
    atomicAdd(&hist[b], 1);
    __syncthreads();

    g_chist[(size_t)t * NCH + blk] = hist[t];

    grid_barrier(&g_barH, NCH);

    // ---- offset scan (each block redundantly; thread t = bucket t) ----
#pragma unroll
    for (int i = 0; i < 8; i++) wcnt[t + i * 1024] = 0u;

    const int4* cp = (const int4*)(g_chist + t * 8);
    int4 v0 = cp[0], v1 = cp[1];
    int vals[8] = {v0.x, v0.y, v0.z, v0.w, v1.x, v1.y, v1.z, v1.w};
    int s = vals[0] + vals[1] + vals[2] + vals[3] +
            vals[4] + vals[5] + vals[6] + vals[7];

    int inc = s;
#pragma unroll
    for (int o = 1; o < 32; o <<= 1) {
        int n = __shfl_up_sync(~0u, inc, o);
        if (lane >= o) inc += n;
    }
    if (lane == 31) warp_sh[warp] = inc;
    __syncthreads();
    if (warp == 0) {
        int ws = warp_sh[lane];
        int wi = ws;
#pragma unroll
        for (int o = 1; o < 32; o <<= 1) {
            int n = __shfl_up_sync(~0u, wi, o);
            if (lane >= o) wi += n;
        }
        warp_sh[lane] = wi - ws;
    }
    __syncthreads();

    int run = warp_sh[warp] + inc - s;   // global start of bucket t
    if (blk == 0) {
        g_off[t] = run;
        if (t == 0) g_off[NB] = NR;
    }
    int myoff = 0;
#pragma unroll
    for (int i = 0; i < 8; i++) {
        if (i == blk) myoff = run;
        run += vals[i];
    }
    choff_sh[t] = myoff;
    __syncthreads();   // wcnt zero + choff_sh visible

    // ---- stable scatter: per-warp uint8 counts + dp4a cross-warp sums ----
    unsigned mask = __match_any_sync(~0u, b);
    const int leader = __ffs(mask) - 1;
    const int lr = __popc(mask & ((1u << lane) - 1));
    if (lane == leader)
        ((unsigned char*)wcnt)[b * 32 + warp] = (unsigned char)__popc(mask);
    __syncthreads();

    const unsigned* row = wcnt + b * 8;
    unsigned cross = 0u;
    const int kf = warp >> 2;
    for (int k = 0; k < kf; k++) cross = __dp4a(row[k], 0x01010101u, cross);
    const unsigned pmask = (1u << ((warp & 3) * 8)) - 1u;
    cross = __dp4a(row[kf] & pmask, 0x01010101u, cross);

    const int pos = choff_sh[b] + (int)cross + lr;
    g_ord[pos]  = j;
    g_dord[pos] = dv;

    grid_barrier(&g_barH, NCH);   // also makes wcnt reusable as staging

    // ---- in-bucket value sort: 256 warps x 4 buckets; smem-staged ranks ----
    float* sdv = (float*)wcnt;                 // 32 warps x 64 floats = 8 KB
    int*   sdi = (int*)wcnt + 2048;            // 32 warps x 64 ints   = 8 KB
    float* mydv = sdv + warp * 64;
    int*   mydi = sdi + warp * 64;

#pragma unroll
    for (int q = 0; q < 4; q++) {
        const int b2 = blk * 128 + warp * 4 + q;
        const int s0 = g_off[b2];
        const int n  = g_off[b2 + 1] - s0;
        if (n <= 64) {
            for (int e = lane; e < n; e += 32) {
                mydv[e] = g_dord[s0 + e];
                mydi[e] = g_ord[s0 + e];
            }
            __syncwarp();
            for (int e = lane; e < n; e += 32) {
                const float dk = mydv[e];
                const int   ik = mydi[e];
                int rank = 0;
                for (int e2 = 0; e2 < n; e2++) {
                    const float d2 = mydv[e2];    // broadcast LDS
                    const int   i2 = mydi[e2];
                    rank += (d2 < dk) || (d2 == dk && i2 < ik);
                }
                g_dord2[s0 + rank] = dk;
                g_ord2[s0 + rank]  = ik;
            }
            __syncwarp();
        } else {
            // fallback (rare): global rank
            for (int e = lane; e < n; e += 32) {
                const float dk = g_dord[s0 + e];
                const int   ik = g_ord[s0 + e];
                int rank = 0;
                for (int e2 = 0; e2 < n; e2++) {
                    const float d2 = g_dord[s0 + e2];
                    const int   i2 = g_ord[s0 + e2];
                    rank += (d2 < dk) || (d2 == dk && i2 < ik);
                }
                g_dord2[s0 + rank] = dk;
                g_ord2[s0 + rank]  = ik;
            }
        }
    }
}

// ---------------------------------------------------------------------------
// K3: per-segment scans over the value-sorted order (MLP-batched)
// + last-block-done inline segscan. 128 blocks x 256 threads.
// ---------------------------------------------------------------------------
__global__ __launch_bounds__(256) void scan_kernel()
{
    __shared__ float wh[SEGSZ][65];   // 16.6 KB
    __shared__ float Bsh[SEGSZ], Dsh[SEGSZ];
    __shared__ int islast_sh;

    const int g = blockIdx.x;
    const int t = threadIdx.x;
    const int base = g * SEGSZ;

    {
        const int row = t >> 2, q = t & 3;   // 4 threads per row, 4 float4 each
        const int src = g_ord2[base + row];
        const float4* wr = (const float4*)(g_Wh + (size_t)src * F_OUT) + q * 4;
#pragma unroll
        for (int i = 0; i < 4; i++) {
            float4 v = wr[i];
            wh[row][q * 16 + i * 4 + 0] = v.x;
            wh[row][q * 16 + i * 4 + 1] = v.y;
            wh[row][q * 16 + i * 4 + 2] = v.z;
            wh[row][q * 16 + i * 4 + 3] = v.w;
        }
    }
    if (t < SEGSZ) {
        const float dmax = decf(g_dmax_u);
        float dv = g_dord2[base + t];
        Bsh[t] = __expf(dv - dmax);
        Dsh[t] = __expf(ALPHA * (dv - dmax));
    }
    __syncthreads();

    if (t < 65) {
        float acc = 0.f;
#pragma unroll
        for (int kb = 0; kb < SEGSZ; kb += 8) {
            float xv[8], dw[8];
#pragma unroll
            for (int i = 0; i < 8; i++) {
                xv[i] = (t < 64) ? wh[kb + i][t] : 1.f;
                dw[i] = Dsh[kb + i];
            }
#pragma unroll
            for (int i = 0; i < 8; i++) {
                g_locPre[(size_t)(base + kb + i) * LDW + t] = acc;
                acc = fmaf(dw[i], xv[i], acc);
            }
        }
        g_segPre[g * LDW + t] = acc;
    } else if (t >= 128 && t < 193) {
        const int tt = t - 128;
        float acc2 = 0.f;
#pragma unroll
        for (int kb = SEGSZ - 8; kb >= 0; kb -= 8) {
            float xv[8], bw[8];
#pragma unroll
            for (int i = 7; i >= 0; i--) {
                xv[i] = (tt < 64) ? wh[kb + i][tt] : 1.f;
                bw[i] = Bsh[kb + i];
            }
#pragma unroll
            for (int i = 7; i >= 0; i--) {
                acc2 = fmaf(bw[i], xv[i], acc2);
                g_locSuf[(size_t)(base + kb + i) * LDW + tt] = acc2;
            }
        }
        g_segSuf[g * LDW + tt] = acc2;
    }

    // ---- last-block-done: inline segscan ----
    __syncthreads();
    if (t == 0) {
        __threadfence();
        unsigned old = atomicAdd(&g_scanDone, 1u);
        islast_sh = ((old % NSEG) == (NSEG - 1)) ? 1 : 0;
    }
    __syncthreads();
    if (!islast_sh) return;
    __threadfence();

    if (t < 65) {
        float acc = 0.f;
#pragma unroll
        for (int half = 0; half < 2; half++) {
            float vp[64];
#pragma unroll
            for (int g2 = 0; g2 < 64; g2++)
                vp[g2] = g_segPre[(half * 64 + g2) * LDW + t];
#pragma unroll
            for (int g2 = 0; g2 < 64; g2++) {
                g_offPre[(half * 64 + g2) * LDW + t] = acc;
                acc += vp[g2];
            }
        }
        g_offPre[NSEG * LDW + t] = acc;
    } else if (t >= 128 && t < 193) {
        const int tt = t - 128;
        float acc2 = 0.f;
#pragma unroll
        for (int half = 1; half >= 0; half--) {
            float vs[64];
#pragma unroll
            for (int g2 = 0; g2 < 64; g2++)
                vs[g2] = g_segSuf[(half * 64 + g2) * LDW + tt];
#pragma unroll
            for (int g2 = 63; g2 >= 0; g2--) {
                g_offSuf[(half * 64 + g2) * LDW + tt] = acc2;
                acc2 += vs[g2];
            }
        }
    }
}

// ---------------------------------------------------------------------------
// K4: warp-per-row combine. Split via bucket lookup + ballot-count over the
// value-sorted bucket (1-2 parallel coalesced loads). No dependent chain.
// ---------------------------------------------------------------------------
__global__ __launch_bounds__(256) void final_kernel(float* __restrict__ out)
{
    const int t = threadIdx.x;
    const int w = t >> 5, l = t & 31;
    const int i = blockIdx.x * 8 + w;

    const float dmax  = decf(g_dmax_u);
    const float dmin  = decf(g_dmin_u);
    const float scale = mkscale(dmin, dmax);

    const float s  = g_s[i];
    const float xm = s + dmax;
    const float m  = fmaxf(xm, ALPHA * xm);
    const float A  = __expf(xm - m);
    const float C  = __expf(ALPHA * xm - m);
    const float th = -s;

    // split position: count of d_j <= th; bucket is value-sorted, so count via
    // 32-wide ballots with early exit at the crossing.
    const float tb = bval(th, dmin, scale);
    int tpos = 0;
    if (tb >= 0.f) {
        const int b = (int)tb;
        const int lo = g_off[b], hi = g_off[b + 1];
        int cnt = 0;
        for (int e0 = lo; e0 < hi; e0 += 32) {
            const int e = e0 + l;
            const bool in = (e < hi) && (g_dord2[e] <= th);
            const unsigned bal = __ballot_sync(~0u, in);
            cnt += __popc(bal);
            if (bal != 0xFFFFFFFFu) break;   // sorted: crossing found
        }
        tpos = lo + cnt;
    }

    float pre_l, pre_h, pre_z;
    if (tpos < NR) {
        const int sg = tpos >> 6;
        const float* oP = g_offPre + sg * LDW;
        const float* lP = g_locPre + (size_t)tpos * LDW;
        pre_l = oP[l] + lP[l];
        pre_h = oP[32 + l] + lP[32 + l];
        pre_z = oP[64] + lP[64];
    } else {
        const float* oP = g_offPre + NSEG * LDW;
        pre_l = oP[l];
        pre_h = oP[32 + l];
        pre_z = oP[64];
    }

    float suf_l = 0.f, suf_h = 0.f, suf_z = 0.f;
    if (tpos < NR) {
        const int sg = tpos >> 6;
        const float* oS = g_offSuf + sg * LDW;
        const float* lS = g_locSuf + (size_t)tpos * LDW;
        suf_l = oS[l] + lS[l];
        suf_h = oS[32 + l] + lS[32 + l];
        suf_z = oS[64] + lS[64];
    }

    const float Z  = fmaf(A, suf_z, C * pre_z);
    const float rz = 1.f / Z;
    const float v1 = fmaf(A, suf_l, C * pre_l) * rz;
    const float v2 = fmaf(A, suf_h, C * pre_h) * rz;

    out[(size_t)i * F_OUT + l]      = (v1 > 0.f) ? v1 : (__expf(v1) - 1.f);
    out[(size_t)i * F_OUT + 32 + l] = (v2 > 0.f) ? v2 : (__expf(v2) - 1.f);
}

// ---------------------------------------------------------------------------
extern "C" void kernel_launch(void* const* d_in, const int* in_sizes, int n_in,
                              void* d_out, int out_size)
{
    const float* h = (const float*)d_in[0];
    const float* W = (const float*)d_in[1];
    const float* a = (const float*)d_in[2];
    float* out = (float*)d_out;

    wh_kernel<<<NR / 64, 256>>>(h, W, a);
    histscatter_kernel<<<NCH, 1024>>>();
    scan_kernel<<<NSEG, 256>>>();
    final_kernel<<<NR / 8, 256>>>(out);
}